// round 1
// baseline (speedup 1.0000x reference)
#include <cuda_runtime.h>

#define HW   4096
#define NB   16
#define NHD  8
#define ATTN_SCALE 0.17677669529663687f   // (256/8)^-0.5

typedef unsigned long long ull;

// Scratch (allocation-free): qkv planes [b][192][HW], attention out [b][64][HW]
__device__ float g_qkv[NB * 192 * HW];
__device__ float g_att[NB * 64 * HW];

__device__ __forceinline__ ull pack2(float lo, float hi) {
    ull r; asm("mov.b64 %0, {%1, %2};" : "=l"(r) : "f"(lo), "f"(hi)); return r;
}
__device__ __forceinline__ float2 unpack2(ull v) {
    float2 f; asm("mov.b64 {%0, %1}, %2;" : "=f"(f.x), "=f"(f.y) : "l"(v)); return f;
}
__device__ __forceinline__ ull fma2(ull a, ull b, ull c) {
    ull d; asm("fma.rn.f32x2 %0, %1, %2, %3;" : "=l"(d) : "l"(a), "l"(b), "l"(c)); return d;
}

// ---------------------------------------------------------------------------
// Per-pixel GEMM: O[b][ch][p] = sum_k A[b][k][p] * Wt[ch][k] + bias[ch]
// Each thread: 4 pixels (packed as 2x f32x2) x NCH channels.
// Weights duplicated into smem as {w,w} pairs so one LDS.128 feeds 4 f32x2 FMAs.
// grid: (HW/1024, Ntot/NCH, B), block 256.
// ---------------------------------------------------------------------------
template<int K, int NCH, int NTOT>
__global__ void __launch_bounds__(256) gemm_px(
    const float* __restrict__ A, const float* __restrict__ Wt,
    const float* __restrict__ bias, float* __restrict__ O)
{
    __shared__ __align__(16) ull sw[NCH * K];
    const int b   = blockIdx.z;
    const int ch0 = blockIdx.y * NCH;
    const int tid = threadIdx.x;

    for (int i = tid; i < NCH * K; i += 256) {
        float w = Wt[(ch0 + i / K) * K + (i % K)];
        sw[i] = pack2(w, w);
    }
    __syncthreads();

    const float* a = A + (size_t)b * K * HW + blockIdx.x * 1024 + tid;

    ull acc[NCH][2];
    #pragma unroll
    for (int j = 0; j < NCH; j++) { acc[j][0] = 0ull; acc[j][1] = 0ull; }

    #pragma unroll 2
    for (int k = 0; k < K; k += 2) {
        float x0a = a[k * HW];
        float x0b = a[k * HW + 256];
        float x0c = a[k * HW + 512];
        float x0d = a[k * HW + 768];
        float x1a = a[(k + 1) * HW];
        float x1b = a[(k + 1) * HW + 256];
        float x1c = a[(k + 1) * HW + 512];
        float x1d = a[(k + 1) * HW + 768];
        ull xa0 = pack2(x0a, x0b), xb0 = pack2(x0c, x0d);
        ull xa1 = pack2(x1a, x1b), xb1 = pack2(x1c, x1d);
        #pragma unroll
        for (int j = 0; j < NCH; j++) {
            ulonglong2 w = reinterpret_cast<const ulonglong2*>(sw)[(j * K + k) >> 1];
            acc[j][0] = fma2(xa0, w.x, acc[j][0]);
            acc[j][1] = fma2(xb0, w.x, acc[j][1]);
            acc[j][0] = fma2(xa1, w.y, acc[j][0]);
            acc[j][1] = fma2(xb1, w.y, acc[j][1]);
        }
    }

    #pragma unroll
    for (int j = 0; j < NCH; j++) {
        float bb = bias[ch0 + j];
        float2 v0 = unpack2(acc[j][0]);
        float2 v1 = unpack2(acc[j][1]);
        float* orow = O + ((size_t)b * NTOT + ch0 + j) * HW + blockIdx.x * 1024 + tid;
        orow[0]   = v0.x + bb;
        orow[256] = v0.y + bb;
        orow[512] = v1.x + bb;
        orow[768] = v1.y + bb;
    }
}

// ---------------------------------------------------------------------------
// Fused unfold + depthwise conv + 9-tap attention.
// Combined kernel per channel c, tap j:  W[c,j,delta] = conv1_w[9c+j,delta] + (delta==j)
//   k[c][j](p) = sum_d kk[c](p+d) * W[c,j,d] + bias[9c+j] + rpb[n,j]
//   v[c][j](p) = sum_d vv[c](p+d) * W[c,j,d] + bias[9c+j]
//   out[c]     = softmax_j( sum_c q[c]*k[c][j] ) . v[c][:]
// CTA: one (b, head), 32x16 pixel tile; each thread handles 2 pixels (rows
// ty and ty+8) packed as f32x2 so every weight LDS feeds a 2-wide FMA.
// grid: (2, 4, B*NH), block 256.
// ---------------------------------------------------------------------------
__global__ void __launch_bounds__(256) attn_kernel(
    const float* __restrict__ conv1_w, const float* __restrict__ conv_b,
    const float* __restrict__ conv1_b, const float* __restrict__ rpb)
{
    __shared__ float kk_s[8][18][34];
    __shared__ float vv_s[8][18][34];
    __shared__ __align__(16) ull sW2[648];   // duplicated combined weights
    __shared__ float sb[72];
    __shared__ float srpb[9];

    const int tid = threadIdx.x;
    const int b   = blockIdx.z >> 3;
    const int n   = blockIdx.z & 7;
    const int w0  = blockIdx.x * 32;
    const int h0  = blockIdx.y * 16;

    const float* kbase = g_qkv + ((size_t)b * 192 + n * 24 + 8) * HW;
    const float* vbase = kbase + 8 * HW;

    // halo'd tile load (zero padding outside [0,64)^2)
    for (int i = tid; i < 8 * 18 * 34; i += 256) {
        int c = i / (18 * 34);
        int r = i - c * (18 * 34);
        int y = r / 34, x = r - y * 34;
        int gh = h0 + y - 1, gw = w0 + x - 1;
        float kv = 0.f, vv = 0.f;
        if ((unsigned)gh < 64u && (unsigned)gw < 64u) {
            int p = gh * 64 + gw;
            kv = kbase[c * HW + p];
            vv = vbase[c * HW + p];
        }
        (&kk_s[0][0][0])[i] = kv;
        (&vv_s[0][0][0])[i] = vv;
    }
    for (int i = tid; i < 648; i += 256) {
        float wv = conv1_w[i];
        if ((i % 9) == ((i / 9) % 9)) wv += 1.0f;   // add unfold identity
        sW2[i] = pack2(wv, wv);
    }
    if (tid < 72) sb[tid] = conv_b[tid] + conv1_b[tid];
    if (tid < 9)  srpb[tid] = rpb[n * 9 + tid];
    __syncthreads();

    const int tx = tid & 31, ty = tid >> 5;          // 32 x 8 threads
    const int pA = (h0 + ty) * 64 + (w0 + tx);
    const int pB = pA + 8 * 64;                       // second pixel: row ty+8

    const float* qbase = g_qkv + ((size_t)b * 192 + n * 24) * HW;
    ull q2[8];
    #pragma unroll
    for (int c = 0; c < 8; c++)
        q2[c] = pack2(qbase[c * HW + pA] * ATTN_SCALE,
                      qbase[c * HW + pB] * ATTN_SCALE);

    ull lg[9];
    #pragma unroll
    for (int j = 0; j < 9; j++) lg[j] = 0ull;

    // logits
    #pragma unroll 1
    for (int c = 0; c < 8; c++) {
        ull win[9];
        #pragma unroll
        for (int d = 0; d < 9; d++) {
            int dy = d / 3, dx = d % 3;
            win[d] = pack2(kk_s[c][ty + dy][tx + dx],
                           kk_s[c][ty + 8 + dy][tx + dx]);
        }
        #pragma unroll
        for (int j = 0; j < 9; j++) {
            float kb = sb[c * 9 + j] + srpb[j];
            ull kv = pack2(kb, kb);
            #pragma unroll
            for (int d = 0; d < 9; d++)
                kv = fma2(win[d], sW2[(c * 9 + j) * 9 + d], kv);
            lg[j] = fma2(q2[c], kv, lg[j]);
        }
    }

    // two independent softmaxes (one per packed pixel)
    float lA[9], lB[9];
    #pragma unroll
    for (int j = 0; j < 9; j++) { float2 f = unpack2(lg[j]); lA[j] = f.x; lB[j] = f.y; }
    float mA = lA[0], mB = lB[0];
    #pragma unroll
    for (int j = 1; j < 9; j++) { mA = fmaxf(mA, lA[j]); mB = fmaxf(mB, lB[j]); }
    float sA = 0.f, sB = 0.f;
    #pragma unroll
    for (int j = 0; j < 9; j++) {
        lA[j] = __expf(lA[j] - mA); sA += lA[j];
        lB[j] = __expf(lB[j] - mB); sB += lB[j];
    }
    float rA = 1.0f / sA, rB = 1.0f / sB;
    ull at2[9];
    #pragma unroll
    for (int j = 0; j < 9; j++) at2[j] = pack2(lA[j] * rA, lB[j] * rB);

    // weighted value sum
    float* obase = g_att + ((size_t)b * 64 + n * 8) * HW;
    #pragma unroll 1
    for (int c = 0; c < 8; c++) {
        ull win[9];
        #pragma unroll
        for (int d = 0; d < 9; d++) {
            int dy = d / 3, dx = d % 3;
            win[d] = pack2(vv_s[c][ty + dy][tx + dx],
                           vv_s[c][ty + 8 + dy][tx + dx]);
        }
        ull oacc = 0ull;
        #pragma unroll
        for (int j = 0; j < 9; j++) {
            float vb = sb[c * 9 + j];
            ull vv = pack2(vb, vb);
            #pragma unroll
            for (int d = 0; d < 9; d++)
                vv = fma2(win[d], sW2[(c * 9 + j) * 9 + d], vv);
            oacc = fma2(at2[j], vv, oacc);
        }
        float2 o = unpack2(oacc);
        obase[c * HW + pA] = o.x;
        obase[c * HW + pB] = o.y;
    }
}

// ---------------------------------------------------------------------------
extern "C" void kernel_launch(void* const* d_in, const int* in_sizes, int n_in,
                              void* d_out, int out_size)
{
    (void)in_sizes; (void)n_in; (void)out_size;
    const float* x       = (const float*)d_in[0];
    // d_in[1]=H22, d_in[2]=W22, d_in[3]=relative_pos_index, d_in[4]=relative_coords_table: unused
    const float* qkv_w   = (const float*)d_in[5];   // [192][256]
    const float* qkv_b   = (const float*)d_in[6];   // [192]
    const float* conv_b  = (const float*)d_in[7];   // [72]
    const float* conv1_w = (const float*)d_in[8];   // [72][9]
    const float* conv1_b = (const float*)d_in[9];   // [72]
    const float* rpb     = (const float*)d_in[10];  // [8][9]
    const float* proj_w  = (const float*)d_in[11];  // [256][64]
    const float* proj_b  = (const float*)d_in[12];  // [256]
    float* out = (float*)d_out;

    float* qkv_ptr = nullptr; cudaGetSymbolAddress((void**)&qkv_ptr, g_qkv);
    float* att_ptr = nullptr; cudaGetSymbolAddress((void**)&att_ptr, g_att);

    // 1) QKV: 256 -> 192 per pixel
    gemm_px<256, 12, 192><<<dim3(4, 16, NB), 256>>>(x, qkv_w, qkv_b, qkv_ptr);
    // 2) fused unfold/conv/attention per head
    attn_kernel<<<dim3(2, 4, NB * NHD), 256>>>(conv1_w, conv_b, conv1_b, rpb);
    // 3) proj: 64 -> 256 per pixel
    gemm_px<64, 16, 256><<<dim3(4, 16, NB), 256>>>(att_ptr, proj_w, proj_b, out);
}

// round 5
// speedup vs baseline: 3.0494x; 3.0494x over previous
#include <cuda_runtime.h>
#include <cstdint>

#define HW   4096
#define NB   16
#define ATTN_SCALE 0.17677669529663687f   // (256/8)^-0.5

typedef unsigned long long ull;

// Scratch (allocation-free): qkv planes [b][192][HW], attention out [b][64][HW]
__device__ float g_qkv[NB * 192 * HW];
__device__ float g_att[NB * 64 * HW];

// ---------------- f32x2 helpers (attn kernel) ----------------
__device__ __forceinline__ ull pack2(float lo, float hi) {
    ull r; asm("mov.b64 %0, {%1, %2};" : "=l"(r) : "f"(lo), "f"(hi)); return r;
}
__device__ __forceinline__ float2 unpack2(ull v) {
    float2 f; asm("mov.b64 {%0, %1}, %2;" : "=f"(f.x), "=f"(f.y) : "l"(v)); return f;
}
__device__ __forceinline__ ull fma2(ull a, ull b, ull c) {
    ull d; asm("fma.rn.f32x2 %0, %1, %2, %3;" : "=l"(d) : "l"(a), "l"(b), "l"(c)); return d;
}

// ---------------- mma.sync tf32 helpers (plain sm_103-safe) ----------------
__device__ __forceinline__ uint32_t f2tf32(float f) {
    uint32_t u; asm("cvt.rna.tf32.f32 %0, %1;" : "=r"(u) : "f"(f)); return u;
}
__device__ __forceinline__ void mma_tf32_16x8x8(
    float* d, const uint32_t* a, const uint32_t* b)
{
    asm volatile(
        "mma.sync.aligned.m16n8k8.row.col.f32.tf32.tf32.f32 "
        "{%0,%1,%2,%3}, {%4,%5,%6,%7}, {%8,%9}, {%0,%1,%2,%3};"
        : "+f"(d[0]), "+f"(d[1]), "+f"(d[2]), "+f"(d[3])
        : "r"(a[0]), "r"(a[1]), "r"(a[2]), "r"(a[3]),
          "r"(b[0]), "r"(b[1]));
}
__device__ __forceinline__ void cp16(uint32_t smem_dst, const void* gsrc) {
    asm volatile("cp.async.cg.shared.global [%0], [%1], 16;"
                 :: "r"(smem_dst), "l"(gsrc) : "memory");
}
__device__ __forceinline__ void cp_commit() {
    asm volatile("cp.async.commit_group;" ::: "memory");
}
template <int N>
__device__ __forceinline__ void cp_wait() {
    asm volatile("cp.async.wait_group %0;" :: "n"(N) : "memory");
}

// ---------------------------------------------------------------------------
// Tiled tf32 mma.sync GEMM:
//   O[b][m][px] = sum_k Wt[m][k] * A[b][k][px] + bias[m]
// CTA: 256 thr = 8 warps (2 m x 4 n). CTA tile M=64 x N=128px, K staged 32.
// Warp tile 32x32 via 2x4 mma.m16n8k8 frags per k-chunk of 8.
// Smem: B [32][136] floats (bank-conflict-free frag loads), A [64][36].
// Double-buffered cp.async pipeline.
// grid: (32 px-tiles, MTOT/64, B).
// ---------------------------------------------------------------------------
#define SB_STRIDE 136
#define SA_STRIDE 36
#define SB_STAGE  (32 * SB_STRIDE)            // floats
#define SA_STAGE  (64 * SA_STRIDE)
#define GEMM_SMEM ((2 * (SB_STAGE + SA_STAGE)) * 4)

template<int KDIM, int MTOT>
__global__ void __launch_bounds__(256) gemm_mma(
    const float* __restrict__ A, const float* __restrict__ Wt,
    const float* __restrict__ bias, float* __restrict__ O)
{
    extern __shared__ __align__(16) float sm[];
    float* sB = sm;                    // 2 stages
    float* sA = sm + 2 * SB_STAGE;     // 2 stages

    const int tid  = threadIdx.x;
    const int lane = tid & 31;
    const int wid  = tid >> 5;
    const int wm   = wid >> 2;         // 0..1
    const int wn   = wid & 3;          // 0..3
    const int g    = lane >> 2;        // 0..7
    const int tig  = lane & 3;         // 0..3

    const int b   = blockIdx.z;
    const int m0  = blockIdx.y * 64;
    const int px0 = blockIdx.x * 128;
    const float* Ab = A + (size_t)b * KDIM * HW + px0;

    constexpr int NS = KDIM / 32;

    const uint32_t sb_u = (uint32_t)__cvta_generic_to_shared(sB);
    const uint32_t sa_u = (uint32_t)__cvta_generic_to_shared(sA);

    // ---- async stage loader ----
    auto issue = [&](int s, int buf) {
        const uint32_t bB = sb_u + (uint32_t)buf * (SB_STAGE * 4);
        const uint32_t bA = sa_u + (uint32_t)buf * (SA_STAGE * 4);
        const int k0 = s * 32;
        // B: 32 k-rows x 128 px (32 x 16B chunks per row) = 1024 units
        #pragma unroll
        for (int i = 0; i < 4; i++) {
            int idx = i * 256 + tid;
            int row = idx >> 5, ch = idx & 31;
            cp16(bB + (uint32_t)(row * SB_STRIDE + ch * 4) * 4,
                 Ab + (size_t)(k0 + row) * HW + ch * 4);
        }
        // A: 64 m-rows x 32 k (8 x 16B chunks per row) = 512 units
        #pragma unroll
        for (int i = 0; i < 2; i++) {
            int idx = i * 256 + tid;
            int row = idx >> 3, ch = idx & 7;
            cp16(bA + (uint32_t)(row * SA_STRIDE + ch * 4) * 4,
                 Wt + (size_t)(m0 + row) * KDIM + k0 + ch * 4);
        }
    };

    float d[2][4][4];
    #pragma unroll
    for (int mi = 0; mi < 2; mi++)
        #pragma unroll
        for (int ni = 0; ni < 4; ni++)
            #pragma unroll
            for (int q = 0; q < 4; q++) d[mi][ni][q] = 0.f;

    issue(0, 0); cp_commit();
    if (NS > 1) { issue(1, 1); cp_commit(); }

    for (int s = 0; s < NS; s++) {
        if (s + 1 < NS) cp_wait<1>(); else cp_wait<0>();
        __syncthreads();

        const float* cB = sB + (s & 1) * SB_STAGE;
        const float* cA = sA + (s & 1) * SA_STAGE;

        #pragma unroll
        for (int kc = 0; kc < 4; kc++) {
            uint32_t af[2][4];
            #pragma unroll
            for (int mi = 0; mi < 2; mi++) {
                int base = (wm * 32 + mi * 16 + g) * SA_STRIDE + kc * 8 + tig;
                af[mi][0] = f2tf32(cA[base]);
                af[mi][1] = f2tf32(cA[base + 8 * SA_STRIDE]);
                af[mi][2] = f2tf32(cA[base + 4]);
                af[mi][3] = f2tf32(cA[base + 8 * SA_STRIDE + 4]);
            }
            uint32_t bf[4][2];
            #pragma unroll
            for (int ni = 0; ni < 4; ni++) {
                int base = (kc * 8 + tig) * SB_STRIDE + wn * 32 + ni * 8 + g;
                bf[ni][0] = f2tf32(cB[base]);
                bf[ni][1] = f2tf32(cB[base + 4 * SB_STRIDE]);
            }
            #pragma unroll
            for (int mi = 0; mi < 2; mi++)
                #pragma unroll
                for (int ni = 0; ni < 4; ni++)
                    mma_tf32_16x8x8(d[mi][ni], af[mi], bf[ni]);
        }
        __syncthreads();
        if (s + 2 < NS) { issue(s + 2, s & 1); cp_commit(); }
    }

    // ---- epilogue: bias + float2 stores ----
    #pragma unroll
    for (int mi = 0; mi < 2; mi++) {
        const int chA = m0 + wm * 32 + mi * 16 + g;
        const int chB = chA + 8;
        const float bvA = bias[chA];
        const float bvB = bias[chB];
        float* rowA = O + ((size_t)b * MTOT + chA) * HW + px0;
        float* rowB = O + ((size_t)b * MTOT + chB) * HW + px0;
        #pragma unroll
        for (int ni = 0; ni < 4; ni++) {
            const int n = wn * 32 + ni * 8 + 2 * tig;
            float2 oA = make_float2(d[mi][ni][0] + bvA, d[mi][ni][1] + bvA);
            float2 oB = make_float2(d[mi][ni][2] + bvB, d[mi][ni][3] + bvB);
            *reinterpret_cast<float2*>(rowA + n) = oA;
            *reinterpret_cast<float2*>(rowB + n) = oB;
        }
    }
}

// ---------------------------------------------------------------------------
// Fused unfold + depthwise conv + 9-tap attention (unchanged, known-good).
// ---------------------------------------------------------------------------
__global__ void __launch_bounds__(256) attn_kernel(
    const float* __restrict__ conv1_w, const float* __restrict__ conv_b,
    const float* __restrict__ conv1_b, const float* __restrict__ rpb)
{
    __shared__ float kk_s[8][18][34];
    __shared__ float vv_s[8][18][34];
    __shared__ __align__(16) ull sW2[648];
    __shared__ float sb_[72];
    __shared__ float srpb[9];

    const int tid = threadIdx.x;
    const int b   = blockIdx.z >> 3;
    const int n   = blockIdx.z & 7;
    const int w0  = blockIdx.x * 32;
    const int h0  = blockIdx.y * 16;

    const float* kbase = g_qkv + ((size_t)b * 192 + n * 24 + 8) * HW;
    const float* vbase = kbase + 8 * HW;

    for (int i = tid; i < 8 * 18 * 34; i += 256) {
        int c = i / (18 * 34);
        int r = i - c * (18 * 34);
        int y = r / 34, x = r - y * 34;
        int gh = h0 + y - 1, gw = w0 + x - 1;
        float kv = 0.f, vv = 0.f;
        if ((unsigned)gh < 64u && (unsigned)gw < 64u) {
            int p = gh * 64 + gw;
            kv = kbase[c * HW + p];
            vv = vbase[c * HW + p];
        }
        (&kk_s[0][0][0])[i] = kv;
        (&vv_s[0][0][0])[i] = vv;
    }
    for (int i = tid; i < 648; i += 256) {
        float wv = conv1_w[i];
        if ((i % 9) == ((i / 9) % 9)) wv += 1.0f;
        sW2[i] = pack2(wv, wv);
    }
    if (tid < 72) sb_[tid] = conv_b[tid] + conv1_b[tid];
    if (tid < 9)  srpb[tid] = rpb[n * 9 + tid];
    __syncthreads();

    const int tx = tid & 31, ty = tid >> 5;
    const int pA = (h0 + ty) * 64 + (w0 + tx);
    const int pB = pA + 8 * 64;

    const float* qbase = g_qkv + ((size_t)b * 192 + n * 24) * HW;
    ull q2[8];
    #pragma unroll
    for (int c = 0; c < 8; c++)
        q2[c] = pack2(qbase[c * HW + pA] * ATTN_SCALE,
                      qbase[c * HW + pB] * ATTN_SCALE);

    ull lg[9];
    #pragma unroll
    for (int j = 0; j < 9; j++) lg[j] = 0ull;

    #pragma unroll 1
    for (int c = 0; c < 8; c++) {
        ull win[9];
        #pragma unroll
        for (int d = 0; d < 9; d++) {
            int dy = d / 3, dx = d % 3;
            win[d] = pack2(kk_s[c][ty + dy][tx + dx],
                           kk_s[c][ty + 8 + dy][tx + dx]);
        }
        #pragma unroll
        for (int j = 0; j < 9; j++) {
            float kb = sb_[c * 9 + j] + srpb[j];
            ull kv = pack2(kb, kb);
            #pragma unroll
            for (int d = 0; d < 9; d++)
                kv = fma2(win[d], sW2[(c * 9 + j) * 9 + d], kv);
            lg[j] = fma2(q2[c], kv, lg[j]);
        }
    }

    float lA[9], lB[9];
    #pragma unroll
    for (int j = 0; j < 9; j++) { float2 f = unpack2(lg[j]); lA[j] = f.x; lB[j] = f.y; }
    float mA = lA[0], mB = lB[0];
    #pragma unroll
    for (int j = 1; j < 9; j++) { mA = fmaxf(mA, lA[j]); mB = fmaxf(mB, lB[j]); }
    float sA = 0.f, sB = 0.f;
    #pragma unroll
    for (int j = 0; j < 9; j++) {
        lA[j] = __expf(lA[j] - mA); sA += lA[j];
        lB[j] = __expf(lB[j] - mB); sB += lB[j];
    }
    float rA = 1.0f / sA, rB = 1.0f / sB;
    ull at2[9];
    #pragma unroll
    for (int j = 0; j < 9; j++) at2[j] = pack2(lA[j] * rA, lB[j] * rB);

    float* obase = g_att + ((size_t)b * 64 + n * 8) * HW;
    #pragma unroll 1
    for (int c = 0; c < 8; c++) {
        ull win[9];
        #pragma unroll
        for (int d = 0; d < 9; d++) {
            int dy = d / 3, dx = d % 3;
            win[d] = pack2(vv_s[c][ty + dy][tx + dx],
                           vv_s[c][ty + 8 + dy][tx + dx]);
        }
        ull oacc = 0ull;
        #pragma unroll
        for (int j = 0; j < 9; j++) {
            float vb = sb_[c * 9 + j];
            ull vv = pack2(vb, vb);
            #pragma unroll
            for (int d = 0; d < 9; d++)
                vv = fma2(win[d], sW2[(c * 9 + j) * 9 + d], vv);
            oacc = fma2(at2[j], vv, oacc);
        }
        float2 o = unpack2(oacc);
        obase[c * HW + pA] = o.x;
        obase[c * HW + pB] = o.y;
    }
}

// ---------------------------------------------------------------------------
extern "C" void kernel_launch(void* const* d_in, const int* in_sizes, int n_in,
                              void* d_out, int out_size)
{
    (void)in_sizes; (void)n_in; (void)out_size;
    const float* x       = (const float*)d_in[0];
    const float* qkv_w   = (const float*)d_in[5];   // [192][256]
    const float* qkv_b   = (const float*)d_in[6];   // [192]
    const float* conv_b  = (const float*)d_in[7];   // [72]
    const float* conv1_w = (const float*)d_in[8];   // [72][9]
    const float* conv1_b = (const float*)d_in[9];   // [72]
    const float* rpb     = (const float*)d_in[10];  // [8][9]
    const float* proj_w  = (const float*)d_in[11];  // [256][64]
    const float* proj_b  = (const float*)d_in[12];  // [256]
    float* out = (float*)d_out;

    float* qkv_ptr = nullptr; cudaGetSymbolAddress((void**)&qkv_ptr, g_qkv);
    float* att_ptr = nullptr; cudaGetSymbolAddress((void**)&att_ptr, g_att);

    cudaFuncSetAttribute(gemm_mma<256, 192>,
                         cudaFuncAttributeMaxDynamicSharedMemorySize, GEMM_SMEM);
    cudaFuncSetAttribute(gemm_mma<64, 256>,
                         cudaFuncAttributeMaxDynamicSharedMemorySize, GEMM_SMEM);

    // 1) QKV: 256 -> 192 per pixel (tf32 mma.sync)
    gemm_mma<256, 192><<<dim3(32, 3, NB), 256, GEMM_SMEM>>>(x, qkv_w, qkv_b, qkv_ptr);
    // 2) fused unfold/conv/attention per head
    attn_kernel<<<dim3(2, 4, NB * 8), 256>>>(conv1_w, conv_b, conv1_b, rpb);
    // 3) proj: 64 -> 256 per pixel (tf32 mma.sync)
    gemm_mma<64, 256><<<dim3(32, 4, NB), 256, GEMM_SMEM>>>(att_ptr, proj_w, proj_b, out);
}